// round 4
// baseline (speedup 1.0000x reference)
#include <cuda_runtime.h>
#include <cstddef>

// ---------------------------------------------------------------------------
// HMP hierarchical message passing — R4:
//  * 4 rows/thread f32x2 MLPs, un-duplicated SMEM weights + on-the-fly pack
//    (4x less SMEM traffic per row than R3)
//  * separate scatter kernels (R2 structure), single upfront zero
// ---------------------------------------------------------------------------

typedef unsigned long long ull;

#define N1MAX 250000
#define N2MAX 500000
#define N3MAX 1000000

__device__ float g_h2   [(size_t)N2MAX * 32];
__device__ float g_h3   [(size_t)N3MAX * 32];
__device__ float g_acc3 [(size_t)N3MAX * 32];
__device__ float g_acc2 [(size_t)N2MAX * 32];
__device__ float g_acc1 [(size_t)N1MAX * 32];
__device__ float g_accr [(size_t)N1MAX * 32];
__device__ float g_h1mid[(size_t)N1MAX * 32];

// ---------------------------------------------------------------------------
__device__ __forceinline__ ull pack2(float lo, float hi)
{
    ull p;
    asm("mov.b64 %0, {%1, %2};" : "=l"(p) : "f"(lo), "f"(hi));
    return p;
}
__device__ __forceinline__ void unpack2(ull p, float& lo, float& hi)
{
    asm("mov.b64 {%0, %1}, %2;" : "=f"(lo), "=f"(hi) : "l"(p));
}
__device__ __forceinline__ ull ffma2(ull a, ull b, ull c)
{
    ull d;
    asm("fma.rn.f32x2 %0, %1, %2, %3;" : "=l"(d) : "l"(a), "l"(b), "l"(c));
    return d;
}

__device__ __forceinline__ float tanh_fast(float x)
{
    float cx = fminf(fmaxf(x, -15.f), 15.f);
    float e  = __expf(2.f * cx);
    return __fdividef(e - 1.f, e + 1.f);
}

// ---------------------------------------------------------------------------
__global__ void __launch_bounds__(256) zero_multi_kernel(
    float4* __restrict__ p0, int n0, float4* __restrict__ p1, int n1,
    float4* __restrict__ p2, int n2, float4* __restrict__ p3, int n3,
    float4* __restrict__ p4, int n4)
{
    const float4 z = make_float4(0.f, 0.f, 0.f, 0.f);
    int total = n0 + n1 + n2 + n3 + n4;
    for (int i = blockIdx.x * 256 + threadIdx.x; i < total; i += gridDim.x * 256) {
        int j = i;
        if (j < n0) { p0[j] = z; continue; } j -= n0;
        if (j < n1) { p1[j] = z; continue; } j -= n1;
        if (j < n2) { p2[j] = z; continue; } j -= n2;
        if (j < n3) { p3[j] = z; continue; } j -= n3;
        p4[j] = z;
    }
}

// ---------------------------------------------------------------------------
// 4 rows/thread MLP. x = [ self[r] | blocks from 'other' ], P blocks of 32.
// GATHER: blocks 1,2 = other[gi0[r]], other[gi1[r]]; else block 1 = other[r].
// out[r] = tanh(x@W1+b1)@W2+b2
template<int P, bool GATHER>
__global__ void __launch_bounds__(128) mlp4_kernel(
    const float* __restrict__ self, const float* __restrict__ other,
    const int* __restrict__ gi0, const int* __restrict__ gi1,
    const float* __restrict__ W1, const float* __restrict__ b1,
    const float* __restrict__ W2, const float* __restrict__ b2,
    float* __restrict__ out, int n)
{
    __shared__ __align__(16) float sW1[P * 32 * 32];  // [K][32] fp32, k-major
    __shared__ __align__(16) float sW2[32 * 32];      // [k][j]
    __shared__ float sb1[32], sb2[32];
    for (int t = threadIdx.x; t < P * 32 * 32; t += 128) sW1[t] = W1[t];
    for (int t = threadIdx.x; t < 32 * 32; t += 128)     sW2[t] = W2[t];
    if (threadIdx.x < 32) { sb1[threadIdx.x] = b1[threadIdx.x];
                            sb2[threadIdx.x] = b2[threadIdx.x]; }
    __syncthreads();

    int t  = blockIdx.x * 128 + threadIdx.x;
    int r0 = 4 * t;
    if (r0 >= n) return;
    int r1 = min(r0 + 1, n - 1);
    int r2 = min(r0 + 2, n - 1);
    int r3 = min(r0 + 3, n - 1);

    const float4* A0[P]; const float4* A1[P];
    const float4* A2[P]; const float4* A3[P];
    A0[0] = (const float4*)(self + (size_t)r0 * 32);
    A1[0] = (const float4*)(self + (size_t)r1 * 32);
    A2[0] = (const float4*)(self + (size_t)r2 * 32);
    A3[0] = (const float4*)(self + (size_t)r3 * 32);
    if (GATHER) {
        A0[1] = (const float4*)(other + (size_t)gi0[r0] * 32);
        A1[1] = (const float4*)(other + (size_t)gi0[r1] * 32);
        A2[1] = (const float4*)(other + (size_t)gi0[r2] * 32);
        A3[1] = (const float4*)(other + (size_t)gi0[r3] * 32);
        if (P == 3) {
            A0[2] = (const float4*)(other + (size_t)gi1[r0] * 32);
            A1[2] = (const float4*)(other + (size_t)gi1[r1] * 32);
            A2[2] = (const float4*)(other + (size_t)gi1[r2] * 32);
            A3[2] = (const float4*)(other + (size_t)gi1[r3] * 32);
        }
    } else {
        A0[1] = (const float4*)(other + (size_t)r0 * 32);
        A1[1] = (const float4*)(other + (size_t)r1 * 32);
        A2[1] = (const float4*)(other + (size_t)r2 * 32);
        A3[1] = (const float4*)(other + (size_t)r3 * 32);
    }

    // ---------------- layer 1: [4 x P*32] @ [P*32 x 32] ----------------
    ull acc[2][32];   // [pair: (r0,r1) / (r2,r3)][output j]
#pragma unroll
    for (int j = 0; j < 32; j++) {
        float b = sb1[j];
        acc[0][j] = pack2(b, b);
        acc[1][j] = pack2(b, b);
    }

#pragma unroll
    for (int p = 0; p < P; p++) {
#pragma unroll 1
        for (int k4 = 0; k4 < 8; k4++) {
            float4 v0 = A0[p][k4];
            float4 v1 = A1[p][k4];
            float4 v2 = A2[p][k4];
            float4 v3 = A3[p][k4];
            ull xa[4], xb[4];
            xa[0] = pack2(v0.x, v1.x); xb[0] = pack2(v2.x, v3.x);
            xa[1] = pack2(v0.y, v1.y); xb[1] = pack2(v2.y, v3.y);
            xa[2] = pack2(v0.z, v1.z); xb[2] = pack2(v2.z, v3.z);
            xa[3] = pack2(v0.w, v1.w); xb[3] = pack2(v2.w, v3.w);
#pragma unroll
            for (int kk = 0; kk < 4; kk++) {
                const float4* wr = (const float4*)(sW1 + ((p * 8 + k4) * 4 + kk) * 32);
                ull x0 = xa[kk], x1 = xb[kk];
#pragma unroll
                for (int jq = 0; jq < 8; jq++) {
                    float4 w = wr[jq];
                    ull wx = pack2(w.x, w.x);
                    ull wy = pack2(w.y, w.y);
                    ull wz = pack2(w.z, w.z);
                    ull ww = pack2(w.w, w.w);
                    acc[0][4*jq+0] = ffma2(x0, wx, acc[0][4*jq+0]);
                    acc[1][4*jq+0] = ffma2(x1, wx, acc[1][4*jq+0]);
                    acc[0][4*jq+1] = ffma2(x0, wy, acc[0][4*jq+1]);
                    acc[1][4*jq+1] = ffma2(x1, wy, acc[1][4*jq+1]);
                    acc[0][4*jq+2] = ffma2(x0, wz, acc[0][4*jq+2]);
                    acc[1][4*jq+2] = ffma2(x1, wz, acc[1][4*jq+2]);
                    acc[0][4*jq+3] = ffma2(x0, ww, acc[0][4*jq+3]);
                    acc[1][4*jq+3] = ffma2(x1, ww, acc[1][4*jq+3]);
                }
            }
        }
    }

    // tanh (both pairs)
#pragma unroll
    for (int j = 0; j < 32; j++) {
        float u, v;
        unpack2(acc[0][j], u, v);
        acc[0][j] = pack2(tanh_fast(u), tanh_fast(v));
        unpack2(acc[1][j], u, v);
        acc[1][j] = pack2(tanh_fast(u), tanh_fast(v));
    }

    // ---------------- layer 2, chunked (8 outputs at a time) ------------
    float4* O0 = (float4*)(out + (size_t)r0 * 32);
    float4* O1 = (float4*)(out + (size_t)r1 * 32);
    float4* O2 = (float4*)(out + (size_t)r2 * 32);
    float4* O3 = (float4*)(out + (size_t)r3 * 32);
    bool w1 = (r0 + 1 < n), w2 = (r0 + 2 < n), w3 = (r0 + 3 < n);

#pragma unroll 1
    for (int jc = 0; jc < 4; jc++) {
        ull o0[8], o1[8];
#pragma unroll
        for (int m = 0; m < 8; m++) {
            float b = sb2[jc * 8 + m];
            o0[m] = pack2(b, b);
            o1[m] = pack2(b, b);
        }
#pragma unroll 8
        for (int k = 0; k < 32; k++) {
            const float4* wr = (const float4*)(sW2 + k * 32 + jc * 8);
            float4 wA = wr[0];
            float4 wB = wr[1];
            ull h0 = acc[0][k], h1 = acc[1][k];
            ull w;
            w = pack2(wA.x, wA.x); o0[0] = ffma2(h0, w, o0[0]); o1[0] = ffma2(h1, w, o1[0]);
            w = pack2(wA.y, wA.y); o0[1] = ffma2(h0, w, o0[1]); o1[1] = ffma2(h1, w, o1[1]);
            w = pack2(wA.z, wA.z); o0[2] = ffma2(h0, w, o0[2]); o1[2] = ffma2(h1, w, o1[2]);
            w = pack2(wA.w, wA.w); o0[3] = ffma2(h0, w, o0[3]); o1[3] = ffma2(h1, w, o1[3]);
            w = pack2(wB.x, wB.x); o0[4] = ffma2(h0, w, o0[4]); o1[4] = ffma2(h1, w, o1[4]);
            w = pack2(wB.y, wB.y); o0[5] = ffma2(h0, w, o0[5]); o1[5] = ffma2(h1, w, o1[5]);
            w = pack2(wB.z, wB.z); o0[6] = ffma2(h0, w, o0[6]); o1[6] = ffma2(h1, w, o1[6]);
            w = pack2(wB.w, wB.w); o0[7] = ffma2(h0, w, o0[7]); o1[7] = ffma2(h1, w, o1[7]);
        }

        float va[8], vb[8], vc[8], vd[8];
#pragma unroll
        for (int m = 0; m < 8; m++) {
            unpack2(o0[m], va[m], vb[m]);
            unpack2(o1[m], vc[m], vd[m]);
        }
        O0[jc * 2]     = make_float4(va[0], va[1], va[2], va[3]);
        O0[jc * 2 + 1] = make_float4(va[4], va[5], va[6], va[7]);
        if (w1) {
            O1[jc * 2]     = make_float4(vb[0], vb[1], vb[2], vb[3]);
            O1[jc * 2 + 1] = make_float4(vb[4], vb[5], vb[6], vb[7]);
        }
        if (w2) {
            O2[jc * 2]     = make_float4(vc[0], vc[1], vc[2], vc[3]);
            O2[jc * 2 + 1] = make_float4(vc[4], vc[5], vc[6], vc[7]);
        }
        if (w3) {
            O3[jc * 2]     = make_float4(vd[0], vd[1], vd[2], vd[3]);
            O3[jc * 2 + 1] = make_float4(vd[4], vd[5], vd[6], vd[7]);
        }
    }
}

// ---------------------------------------------------------------------------
// acc[i0[r]] += src[r]; acc[i1[r]] += src[r]   (row-wise float4 atomics)
__global__ void __launch_bounds__(256) scatter2_kernel(
    const float* __restrict__ src,
    const int* __restrict__ i0, const int* __restrict__ i1,
    float* __restrict__ acc, int n)
{
    int r = blockIdx.x * 256 + threadIdx.x;
    if (r >= n) return;
    const float4* s = (const float4*)(src + (size_t)r * 32);
    float4* d0 = (float4*)(acc + (size_t)i0[r] * 32);
    float4* d1 = (float4*)(acc + (size_t)i1[r] * 32);
#pragma unroll
    for (int q = 0; q < 8; q++) {
        float4 v = s[q];
        atomicAdd(d0 + q, v);
        atomicAdd(d1 + q, v);
    }
}

// acc[dstidx[r]] += src[srcidx[r]]
__global__ void __launch_bounds__(256) scatter1_kernel(
    const float* __restrict__ src,
    const int* __restrict__ srcidx, const int* __restrict__ dstidx,
    float* __restrict__ acc, int n)
{
    int r = blockIdx.x * 256 + threadIdx.x;
    if (r >= n) return;
    const float4* s = (const float4*)(src + (size_t)srcidx[r] * 32);
    float4* d = (float4*)(acc + (size_t)dstidx[r] * 32);
#pragma unroll
    for (int q = 0; q < 8; q++) atomicAdd(d + q, s[q]);
}

// ---------------------------------------------------------------------------
static inline int nblk256(int n) { return (n + 255) / 256; }
static inline int nblk4(int n)   { return (n + 511) / 512; }  // 128 thr x 4 rows

extern "C" void kernel_launch(void* const* d_in, const int* in_sizes, int n_in,
                              void* d_out, int out_size)
{
    const float* h1     = (const float*)d_in[0];
    const float* h2     = (const float*)d_in[1];
    const float* h3     = (const float*)d_in[2];
    const float* h4     = (const float*)d_in[3];
    const float* upW1   = (const float*)d_in[4];
    const float* upb1   = (const float*)d_in[5];
    const float* upW2   = (const float*)d_in[6];
    const float* upb2   = (const float*)d_in[7];
    const float* dnW1   = (const float*)d_in[8];
    const float* dnb1   = (const float*)d_in[9];
    const float* dnW2   = (const float*)d_in[10];
    const float* dnb2   = (const float*)d_in[11];
    const float* rW1    = (const float*)d_in[12];
    const float* rb1    = (const float*)d_in[13];
    const float* rW2    = (const float*)d_in[14];
    const float* rb2    = (const float*)d_in[15];
    const int* idx2_0   = (const int*)d_in[16];
    const int* idx2_1   = (const int*)d_in[17];
    const int* idx3_0   = (const int*)d_in[18];
    const int* idx3_1   = (const int*)d_in[19];
    const int* idx4_0   = (const int*)d_in[20];
    const int* idx4_1   = (const int*)d_in[21];
    const int* ring_src = (const int*)d_in[22];
    const int* ring_dst = (const int*)d_in[23];

    const int N1 = in_sizes[0] / 32;
    const int N2 = in_sizes[1] / 32;
    const int N3 = in_sizes[2] / 32;
    const int N4 = in_sizes[3] / 32;
    const int ER = in_sizes[22];
    const int NR = out_size / 32 - (N1 + N2 + N3 + N4);

    float* out  = (float*)d_out;
    float* out1 = out;
    float* out2 = out1 + (size_t)N1 * 32;
    float* out3 = out2 + (size_t)N2 * 32;
    float* out4 = out3 + (size_t)N3 * 32;
    float* outR = out4 + (size_t)N4 * 32;

    float *h2buf, *h3buf, *acc3, *acc2, *acc1, *accr, *h1mid;
    cudaGetSymbolAddress((void**)&h2buf, g_h2);
    cudaGetSymbolAddress((void**)&h3buf, g_h3);
    cudaGetSymbolAddress((void**)&acc3,  g_acc3);
    cudaGetSymbolAddress((void**)&acc2,  g_acc2);
    cudaGetSymbolAddress((void**)&acc1,  g_acc1);
    cudaGetSymbolAddress((void**)&accr,  g_accr);
    cudaGetSymbolAddress((void**)&h1mid, g_h1mid);

    // ---- zero all accumulators once ----
    zero_multi_kernel<<<2048, 256>>>(
        (float4*)acc3, N3 * 8, (float4*)acc2, N2 * 8,
        (float4*)acc1, N1 * 8, (float4*)accr, N1 * 8,
        (float4*)outR, NR * 8);

    // ---- up pass ----
    mlp4_kernel<3, true><<<nblk4(N2), 128>>>(h2, h1, idx2_0, idx2_1,
        upW1 + 0 * 96 * 32, upb1 + 0 * 32, upW2 + 0 * 1024, upb2 + 0 * 32,
        h2buf, N2);
    mlp4_kernel<3, true><<<nblk4(N3), 128>>>(h3, h2buf, idx3_0, idx3_1,
        upW1 + 1 * 96 * 32, upb1 + 1 * 32, upW2 + 1 * 1024, upb2 + 1 * 32,
        h3buf, N3);
    mlp4_kernel<3, true><<<nblk4(N4), 128>>>(h4, h3buf, idx4_0, idx4_1,
        upW1 + 2 * 96 * 32, upb1 + 2 * 32, upW2 + 2 * 1024, upb2 + 2 * 32,
        out4, N4);

    // ---- down pass ----
    scatter2_kernel<<<nblk256(N4), 256>>>(out4, idx4_0, idx4_1, acc3, N4);
    mlp4_kernel<2, false><<<nblk4(N3), 128>>>(h3buf, acc3, 0, 0,
        dnW1 + 2 * 64 * 32, dnb1 + 2 * 32, dnW2 + 2 * 1024, dnb2 + 2 * 32,
        out3, N3);

    scatter2_kernel<<<nblk256(N3), 256>>>(out3, idx3_0, idx3_1, acc2, N3);
    mlp4_kernel<2, false><<<nblk4(N2), 128>>>(h2buf, acc2, 0, 0,
        dnW1 + 1 * 64 * 32, dnb1 + 1 * 32, dnW2 + 1 * 1024, dnb2 + 1 * 32,
        out2, N2);

    scatter2_kernel<<<nblk256(N2), 256>>>(out2, idx2_0, idx2_1, acc1, N2);
    mlp4_kernel<2, false><<<nblk4(N1), 128>>>(h1, acc1, 0, 0,
        dnW1 + 0 * 64 * 32, dnb1 + 0 * 32, dnW2 + 0 * 1024, dnb2 + 0 * 32,
        h1mid, N1);

    // ---- ring ----
    scatter1_kernel<<<nblk256(ER), 256>>>(h1mid, ring_src, ring_dst, outR, ER);
    scatter1_kernel<<<nblk256(ER), 256>>>(outR, ring_dst, ring_src, accr, ER);
    mlp4_kernel<2, false><<<nblk4(N1), 128>>>(h1mid, accr, 0, 0,
        rW1, rb1, rW2, rb2, out1, N1);
}

// round 5
// speedup vs baseline: 1.4710x; 1.4710x over previous
#include <cuda_runtime.h>
#include <cstddef>

// ---------------------------------------------------------------------------
// HMP hierarchical message passing — R5:
//  * j-pair f32x2 MLPs: acc holds (h_2m, h_2m+1) pairs, weights loaded as
//    native un-duplicated pairs from SMEM (8 LDS.128 / k / warp, broadcast),
//    multiplicand is (x_k,x_k) — 1 pack per row per k.
//  * 4 rows/thread, layer 2 in two 16-wide j-chunks (bounded live registers)
//  * separate scatter kernels (R2 structure), single upfront zero
// ---------------------------------------------------------------------------

typedef unsigned long long ull;

#define N1MAX 250000
#define N2MAX 500000
#define N3MAX 1000000

__device__ float g_h2   [(size_t)N2MAX * 32];
__device__ float g_h3   [(size_t)N3MAX * 32];
__device__ float g_acc3 [(size_t)N3MAX * 32];
__device__ float g_acc2 [(size_t)N2MAX * 32];
__device__ float g_acc1 [(size_t)N1MAX * 32];
__device__ float g_accr [(size_t)N1MAX * 32];
__device__ float g_h1mid[(size_t)N1MAX * 32];

// ---------------------------------------------------------------------------
__device__ __forceinline__ ull pack2(float lo, float hi)
{
    ull p;
    asm("mov.b64 %0, {%1, %2};" : "=l"(p) : "f"(lo), "f"(hi));
    return p;
}
__device__ __forceinline__ void unpack2(ull p, float& lo, float& hi)
{
    asm("mov.b64 {%0, %1}, %2;" : "=f"(lo), "=f"(hi) : "l"(p));
}
__device__ __forceinline__ ull ffma2(ull a, ull b, ull c)
{
    ull d;
    asm("fma.rn.f32x2 %0, %1, %2, %3;" : "=l"(d) : "l"(a), "l"(b), "l"(c));
    return d;
}

__device__ __forceinline__ float tanh_fast(float x)
{
    float cx = fminf(fmaxf(x, -15.f), 15.f);
    float e  = __expf(2.f * cx);
    return __fdividef(e - 1.f, e + 1.f);
}

// ---------------------------------------------------------------------------
__global__ void __launch_bounds__(256) zero_multi_kernel(
    float4* __restrict__ p0, int n0, float4* __restrict__ p1, int n1,
    float4* __restrict__ p2, int n2, float4* __restrict__ p3, int n3,
    float4* __restrict__ p4, int n4)
{
    const float4 z = make_float4(0.f, 0.f, 0.f, 0.f);
    int total = n0 + n1 + n2 + n3 + n4;
    for (int i = blockIdx.x * 256 + threadIdx.x; i < total; i += gridDim.x * 256) {
        int j = i;
        if (j < n0) { p0[j] = z; continue; } j -= n0;
        if (j < n1) { p1[j] = z; continue; } j -= n1;
        if (j < n2) { p2[j] = z; continue; } j -= n2;
        if (j < n3) { p3[j] = z; continue; } j -= n3;
        p4[j] = z;
    }
}

// ---------------------------------------------------------------------------
// 4 rows/thread MLP, j-pair layout.
// x = [ self[r] | blocks from 'other' ]; P = 2 or 3 input blocks of 32.
// GATHER: blocks 1,2 = other[gi0[r]], other[gi1[r]]; else block 1 = other[r].
// out[r] = tanh(x@W1+b1)@W2+b2
template<int P, bool GATHER>
__global__ void __launch_bounds__(128) mlp_jp_kernel(
    const float* __restrict__ self, const float* __restrict__ other,
    const int* __restrict__ gi0, const int* __restrict__ gi1,
    const float* __restrict__ W1, const float* __restrict__ b1,
    const float* __restrict__ W2, const float* __restrict__ b2,
    float* __restrict__ out, int n)
{
    __shared__ __align__(16) float sW1[P * 32 * 32];   // [K][32], un-duplicated
    __shared__ __align__(16) float sW2[32 * 32];       // [k][j]
    __shared__ __align__(16) float sb1[32];
    __shared__ __align__(16) float sb2[32];
    for (int t = threadIdx.x; t < P * 32 * 32 / 4; t += 128)
        ((float4*)sW1)[t] = ((const float4*)W1)[t];
    for (int t = threadIdx.x; t < 32 * 32 / 4; t += 128)
        ((float4*)sW2)[t] = ((const float4*)W2)[t];
    if (threadIdx.x < 32) { sb1[threadIdx.x] = b1[threadIdx.x];
                            sb2[threadIdx.x] = b2[threadIdx.x]; }
    __syncthreads();

    int t  = blockIdx.x * 128 + threadIdx.x;
    int r0 = 4 * t;
    if (r0 >= n) return;
    int r1 = min(r0 + 1, n - 1);
    int r2 = min(r0 + 2, n - 1);
    int r3 = min(r0 + 3, n - 1);

    // ---------------- layer 1: [4 x P*32] @ [P*32 x 32] ----------------
    const ull* sb1u = (const ull*)sb1;
    ull a0[16], a1[16], a2[16], a3[16];
#pragma unroll
    for (int m = 0; m < 16; m++) { ull b = sb1u[m]; a0[m] = b; a1[m] = b; a2[m] = b; a3[m] = b; }

#pragma unroll
    for (int p = 0; p < P; p++) {
        const float4* x0;
        const float4* x1;
        const float4* x2;
        const float4* x3;
        if (p == 0) {
            x0 = (const float4*)(self + (size_t)r0 * 32);
            x1 = (const float4*)(self + (size_t)r1 * 32);
            x2 = (const float4*)(self + (size_t)r2 * 32);
            x3 = (const float4*)(self + (size_t)r3 * 32);
        } else if (GATHER) {
            const int* gi = (p == 1) ? gi0 : gi1;
            x0 = (const float4*)(other + (size_t)gi[r0] * 32);
            x1 = (const float4*)(other + (size_t)gi[r1] * 32);
            x2 = (const float4*)(other + (size_t)gi[r2] * 32);
            x3 = (const float4*)(other + (size_t)gi[r3] * 32);
        } else {
            x0 = (const float4*)(other + (size_t)r0 * 32);
            x1 = (const float4*)(other + (size_t)r1 * 32);
            x2 = (const float4*)(other + (size_t)r2 * 32);
            x3 = (const float4*)(other + (size_t)r3 * 32);
        }
#pragma unroll 2
        for (int k4 = 0; k4 < 8; k4++) {
            float4 v0 = x0[k4];
            float4 v1 = x1[k4];
            float4 v2 = x2[k4];
            float4 v3 = x3[k4];
            const float* e0 = (const float*)&v0;
            const float* e1 = (const float*)&v1;
            const float* e2 = (const float*)&v2;
            const float* e3 = (const float*)&v3;
#pragma unroll
            for (int kk = 0; kk < 4; kk++) {
                ull xp0 = pack2(e0[kk], e0[kk]);
                ull xp1 = pack2(e1[kk], e1[kk]);
                ull xp2 = pack2(e2[kk], e2[kk]);
                ull xp3 = pack2(e3[kk], e3[kk]);
                const ulonglong2* wr =
                    (const ulonglong2*)(sW1 + ((p * 8 + k4) * 4 + kk) * 32);
#pragma unroll
                for (int m2 = 0; m2 < 8; m2++) {
                    ulonglong2 w = wr[m2];
                    a0[2*m2]   = ffma2(xp0, w.x, a0[2*m2]);
                    a1[2*m2]   = ffma2(xp1, w.x, a1[2*m2]);
                    a2[2*m2]   = ffma2(xp2, w.x, a2[2*m2]);
                    a3[2*m2]   = ffma2(xp3, w.x, a3[2*m2]);
                    a0[2*m2+1] = ffma2(xp0, w.y, a0[2*m2+1]);
                    a1[2*m2+1] = ffma2(xp1, w.y, a1[2*m2+1]);
                    a2[2*m2+1] = ffma2(xp2, w.y, a2[2*m2+1]);
                    a3[2*m2+1] = ffma2(xp3, w.y, a3[2*m2+1]);
                }
            }
        }
    }

    // tanh on all pairs
#pragma unroll
    for (int m = 0; m < 16; m++) {
        float u, v;
        unpack2(a0[m], u, v); a0[m] = pack2(tanh_fast(u), tanh_fast(v));
        unpack2(a1[m], u, v); a1[m] = pack2(tanh_fast(u), tanh_fast(v));
        unpack2(a2[m], u, v); a2[m] = pack2(tanh_fast(u), tanh_fast(v));
        unpack2(a3[m], u, v); a3[m] = pack2(tanh_fast(u), tanh_fast(v));
    }

    // ---------------- layer 2: two 16-wide j-chunks ----------------
    const ull* sb2u = (const ull*)sb2;
    bool w1 = (r0 + 1 < n), w2 = (r0 + 2 < n), w3 = (r0 + 3 < n);
    float* O0 = out + (size_t)r0 * 32;
    float* O1 = out + (size_t)r1 * 32;
    float* O2 = out + (size_t)r2 * 32;
    float* O3 = out + (size_t)r3 * 32;

#pragma unroll
    for (int jc = 0; jc < 2; jc++) {
        ull o0[8], o1[8], o2[8], o3[8];
#pragma unroll
        for (int m = 0; m < 8; m++) {
            ull b = sb2u[jc * 8 + m];
            o0[m] = b; o1[m] = b; o2[m] = b; o3[m] = b;
        }
#pragma unroll 4
        for (int kp = 0; kp < 16; kp++) {   // k = 2*kp, 2*kp+1
            float ha0, hb0, ha1, hb1, ha2, hb2, ha3, hb3;
            unpack2(a0[kp], ha0, hb0);
            unpack2(a1[kp], ha1, hb1);
            unpack2(a2[kp], ha2, hb2);
            unpack2(a3[kp], ha3, hb3);
#pragma unroll
            for (int kh = 0; kh < 2; kh++) {
                ull xp0 = pack2(kh ? hb0 : ha0, kh ? hb0 : ha0);
                ull xp1 = pack2(kh ? hb1 : ha1, kh ? hb1 : ha1);
                ull xp2 = pack2(kh ? hb2 : ha2, kh ? hb2 : ha2);
                ull xp3 = pack2(kh ? hb3 : ha3, kh ? hb3 : ha3);
                const ulonglong2* wr =
                    (const ulonglong2*)(sW2 + (2 * kp + kh) * 32 + jc * 16);
#pragma unroll
                for (int m2 = 0; m2 < 4; m2++) {
                    ulonglong2 w = wr[m2];
                    o0[2*m2]   = ffma2(xp0, w.x, o0[2*m2]);
                    o1[2*m2]   = ffma2(xp1, w.x, o1[2*m2]);
                    o2[2*m2]   = ffma2(xp2, w.x, o2[2*m2]);
                    o3[2*m2]   = ffma2(xp3, w.x, o3[2*m2]);
                    o0[2*m2+1] = ffma2(xp0, w.y, o0[2*m2+1]);
                    o1[2*m2+1] = ffma2(xp1, w.y, o1[2*m2+1]);
                    o2[2*m2+1] = ffma2(xp2, w.y, o2[2*m2+1]);
                    o3[2*m2+1] = ffma2(xp3, w.y, o3[2*m2+1]);
                }
            }
        }

        // store 16 floats per row for this chunk
        float va[16], vb[16], vc[16], vd[16];
#pragma unroll
        for (int m = 0; m < 8; m++) {
            unpack2(o0[m], va[2*m], va[2*m+1]);
            unpack2(o1[m], vb[2*m], vb[2*m+1]);
            unpack2(o2[m], vc[2*m], vc[2*m+1]);
            unpack2(o3[m], vd[2*m], vd[2*m+1]);
        }
        float4* q0 = (float4*)(O0 + jc * 16);
        float4* q1 = (float4*)(O1 + jc * 16);
        float4* q2 = (float4*)(O2 + jc * 16);
        float4* q3 = (float4*)(O3 + jc * 16);
#pragma unroll
        for (int q = 0; q < 4; q++) {
            q0[q] = make_float4(va[4*q], va[4*q+1], va[4*q+2], va[4*q+3]);
            if (w1) q1[q] = make_float4(vb[4*q], vb[4*q+1], vb[4*q+2], vb[4*q+3]);
            if (w2) q2[q] = make_float4(vc[4*q], vc[4*q+1], vc[4*q+2], vc[4*q+3]);
            if (w3) q3[q] = make_float4(vd[4*q], vd[4*q+1], vd[4*q+2], vd[4*q+3]);
        }
    }
}

// ---------------------------------------------------------------------------
// acc[i0[r]] += src[r]; acc[i1[r]] += src[r]   (row-wise float4 atomics)
__global__ void __launch_bounds__(256) scatter2_kernel(
    const float* __restrict__ src,
    const int* __restrict__ i0, const int* __restrict__ i1,
    float* __restrict__ acc, int n)
{
    int r = blockIdx.x * 256 + threadIdx.x;
    if (r >= n) return;
    const float4* s = (const float4*)(src + (size_t)r * 32);
    float4* d0 = (float4*)(acc + (size_t)i0[r] * 32);
    float4* d1 = (float4*)(acc + (size_t)i1[r] * 32);
#pragma unroll
    for (int q = 0; q < 8; q++) {
        float4 v = s[q];
        atomicAdd(d0 + q, v);
        atomicAdd(d1 + q, v);
    }
}

// acc[dstidx[r]] += src[srcidx[r]]
__global__ void __launch_bounds__(256) scatter1_kernel(
    const float* __restrict__ src,
    const int* __restrict__ srcidx, const int* __restrict__ dstidx,
    float* __restrict__ acc, int n)
{
    int r = blockIdx.x * 256 + threadIdx.x;
    if (r >= n) return;
    const float4* s = (const float4*)(src + (size_t)srcidx[r] * 32);
    float4* d = (float4*)(acc + (size_t)dstidx[r] * 32);
#pragma unroll
    for (int q = 0; q < 8; q++) atomicAdd(d + q, s[q]);
}

// ---------------------------------------------------------------------------
static inline int nblk256(int n) { return (n + 255) / 256; }
static inline int nblk4(int n)   { return (n + 511) / 512; }  // 128 thr x 4 rows

extern "C" void kernel_launch(void* const* d_in, const int* in_sizes, int n_in,
                              void* d_out, int out_size)
{
    const float* h1     = (const float*)d_in[0];
    const float* h2     = (const float*)d_in[1];
    const float* h3     = (const float*)d_in[2];
    const float* h4     = (const float*)d_in[3];
    const float* upW1   = (const float*)d_in[4];
    const float* upb1   = (const float*)d_in[5];
    const float* upW2   = (const float*)d_in[6];
    const float* upb2   = (const float*)d_in[7];
    const float* dnW1   = (const float*)d_in[8];
    const float* dnb1   = (const float*)d_in[9];
    const float* dnW2   = (const float*)d_in[10];
    const float* dnb2   = (const float*)d_in[11];
    const float* rW1    = (const float*)d_in[12];
    const float* rb1    = (const float*)d_in[13];
    const float* rW2    = (const float*)d_in[14];
    const float* rb2    = (const float*)d_in[15];
    const int* idx2_0   = (const int*)d_in[16];
    const int* idx2_1   = (const int*)d_in[17];
    const int* idx3_0   = (const int*)d_in[18];
    const int* idx3_1   = (const int*)d_in[19];
    const int* idx4_0   = (const int*)d_in[20];
    const int* idx4_1   = (const int*)d_in[21];
    const int* ring_src = (const int*)d_in[22];
    const int* ring_dst = (const int*)d_in[23];

    const int N1 = in_sizes[0] / 32;
    const int N2 = in_sizes[1] / 32;
    const int N3 = in_sizes[2] / 32;
    const int N4 = in_sizes[3] / 32;
    const int ER = in_sizes[22];
    const int NR = out_size / 32 - (N1 + N2 + N3 + N4);

    float* out  = (float*)d_out;
    float* out1 = out;
    float* out2 = out1 + (size_t)N1 * 32;
    float* out3 = out2 + (size_t)N2 * 32;
    float* out4 = out3 + (size_t)N3 * 32;
    float* outR = out4 + (size_t)N4 * 32;

    float *h2buf, *h3buf, *acc3, *acc2, *acc1, *accr, *h1mid;
    cudaGetSymbolAddress((void**)&h2buf, g_h2);
    cudaGetSymbolAddress((void**)&h3buf, g_h3);
    cudaGetSymbolAddress((void**)&acc3,  g_acc3);
    cudaGetSymbolAddress((void**)&acc2,  g_acc2);
    cudaGetSymbolAddress((void**)&acc1,  g_acc1);
    cudaGetSymbolAddress((void**)&accr,  g_accr);
    cudaGetSymbolAddress((void**)&h1mid, g_h1mid);

    // ---- zero all accumulators once ----
    zero_multi_kernel<<<2048, 256>>>(
        (float4*)acc3, N3 * 8, (float4*)acc2, N2 * 8,
        (float4*)acc1, N1 * 8, (float4*)accr, N1 * 8,
        (float4*)outR, NR * 8);

    // ---- up pass ----
    mlp_jp_kernel<3, true><<<nblk4(N2), 128>>>(h2, h1, idx2_0, idx2_1,
        upW1 + 0 * 96 * 32, upb1 + 0 * 32, upW2 + 0 * 1024, upb2 + 0 * 32,
        h2buf, N2);
    mlp_jp_kernel<3, true><<<nblk4(N3), 128>>>(h3, h2buf, idx3_0, idx3_1,
        upW1 + 1 * 96 * 32, upb1 + 1 * 32, upW2 + 1 * 1024, upb2 + 1 * 32,
        h3buf, N3);
    mlp_jp_kernel<3, true><<<nblk4(N4), 128>>>(h4, h3buf, idx4_0, idx4_1,
        upW1 + 2 * 96 * 32, upb1 + 2 * 32, upW2 + 2 * 1024, upb2 + 2 * 32,
        out4, N4);

    // ---- down pass ----
    scatter2_kernel<<<nblk256(N4), 256>>>(out4, idx4_0, idx4_1, acc3, N4);
    mlp_jp_kernel<2, false><<<nblk4(N3), 128>>>(h3buf, acc3, 0, 0,
        dnW1 + 2 * 64 * 32, dnb1 + 2 * 32, dnW2 + 2 * 1024, dnb2 + 2 * 32,
        out3, N3);

    scatter2_kernel<<<nblk256(N3), 256>>>(out3, idx3_0, idx3_1, acc2, N3);
    mlp_jp_kernel<2, false><<<nblk4(N2), 128>>>(h2buf, acc2, 0, 0,
        dnW1 + 1 * 64 * 32, dnb1 + 1 * 32, dnW2 + 1 * 1024, dnb2 + 1 * 32,
        out2, N2);

    scatter2_kernel<<<nblk256(N2), 256>>>(out2, idx2_0, idx2_1, acc1, N2);
    mlp_jp_kernel<2, false><<<nblk4(N1), 128>>>(h1, acc1, 0, 0,
        dnW1 + 0 * 64 * 32, dnb1 + 0 * 32, dnW2 + 0 * 1024, dnb2 + 0 * 32,
        h1mid, N1);

    // ---- ring ----
    scatter1_kernel<<<nblk256(ER), 256>>>(h1mid, ring_src, ring_dst, outR, ER);
    scatter1_kernel<<<nblk256(ER), 256>>>(outR, ring_dst, ring_src, accr, ER);
    mlp_jp_kernel<2, false><<<nblk4(N1), 128>>>(h1mid, accr, 0, 0,
        rW1, rb1, rW2, rb2, out1, N1);
}

// round 6
// speedup vs baseline: 1.6289x; 1.1073x over previous
#include <cuda_runtime.h>
#include <cstddef>

// ---------------------------------------------------------------------------
// HMP hierarchical message passing — R6:
//  * j-pair f32x2 MLPs, 2 rows/thread, __launch_bounds__(128,4) to force
//    <=128 regs -> 4 blocks/SM (2x occupancy vs R5)
//  * layer 2 in two 16-wide j-chunks
//  * separate scatter kernels, single upfront zero
// ---------------------------------------------------------------------------

typedef unsigned long long ull;

#define N1MAX 250000
#define N2MAX 500000
#define N3MAX 1000000

__device__ float g_h2   [(size_t)N2MAX * 32];
__device__ float g_h3   [(size_t)N3MAX * 32];
__device__ float g_acc3 [(size_t)N3MAX * 32];
__device__ float g_acc2 [(size_t)N2MAX * 32];
__device__ float g_acc1 [(size_t)N1MAX * 32];
__device__ float g_accr [(size_t)N1MAX * 32];
__device__ float g_h1mid[(size_t)N1MAX * 32];

// ---------------------------------------------------------------------------
__device__ __forceinline__ ull pack2(float lo, float hi)
{
    ull p;
    asm("mov.b64 %0, {%1, %2};" : "=l"(p) : "f"(lo), "f"(hi));
    return p;
}
__device__ __forceinline__ void unpack2(ull p, float& lo, float& hi)
{
    asm("mov.b64 {%0, %1}, %2;" : "=f"(lo), "=f"(hi) : "l"(p));
}
__device__ __forceinline__ ull ffma2(ull a, ull b, ull c)
{
    ull d;
    asm("fma.rn.f32x2 %0, %1, %2, %3;" : "=l"(d) : "l"(a), "l"(b), "l"(c));
    return d;
}

__device__ __forceinline__ float tanh_fast(float x)
{
    float cx = fminf(fmaxf(x, -15.f), 15.f);
    float e  = __expf(2.f * cx);
    return __fdividef(e - 1.f, e + 1.f);
}

// ---------------------------------------------------------------------------
__global__ void __launch_bounds__(256) zero_multi_kernel(
    float4* __restrict__ p0, int n0, float4* __restrict__ p1, int n1,
    float4* __restrict__ p2, int n2, float4* __restrict__ p3, int n3,
    float4* __restrict__ p4, int n4)
{
    const float4 z = make_float4(0.f, 0.f, 0.f, 0.f);
    int total = n0 + n1 + n2 + n3 + n4;
    for (int i = blockIdx.x * 256 + threadIdx.x; i < total; i += gridDim.x * 256) {
        int j = i;
        if (j < n0) { p0[j] = z; continue; } j -= n0;
        if (j < n1) { p1[j] = z; continue; } j -= n1;
        if (j < n2) { p2[j] = z; continue; } j -= n2;
        if (j < n3) { p3[j] = z; continue; } j -= n3;
        p4[j] = z;
    }
}

// ---------------------------------------------------------------------------
// 2 rows/thread MLP, j-pair layout, <=128 regs.
// x = [ self[r] | blocks from 'other' ]; P = 2 or 3 input blocks of 32.
// GATHER: blocks 1,2 = other[gi0[r]], other[gi1[r]]; else block 1 = other[r].
// out[r] = tanh(x@W1+b1)@W2+b2
template<int P, bool GATHER>
__global__ void __launch_bounds__(128, 4) mlp_jp2_kernel(
    const float* __restrict__ self, const float* __restrict__ other,
    const int* __restrict__ gi0, const int* __restrict__ gi1,
    const float* __restrict__ W1, const float* __restrict__ b1,
    const float* __restrict__ W2, const float* __restrict__ b2,
    float* __restrict__ out, int n)
{
    __shared__ __align__(16) float sW1[P * 32 * 32];   // [K][32], un-duplicated
    __shared__ __align__(16) float sW2[32 * 32];       // [k][j]
    __shared__ __align__(16) float sb1[32];
    __shared__ __align__(16) float sb2[32];
    for (int t = threadIdx.x; t < P * 32 * 32 / 4; t += 128)
        ((float4*)sW1)[t] = ((const float4*)W1)[t];
    for (int t = threadIdx.x; t < 32 * 32 / 4; t += 128)
        ((float4*)sW2)[t] = ((const float4*)W2)[t];
    if (threadIdx.x < 32) { sb1[threadIdx.x] = b1[threadIdx.x];
                            sb2[threadIdx.x] = b2[threadIdx.x]; }
    __syncthreads();

    int t  = blockIdx.x * 128 + threadIdx.x;
    int r0 = 2 * t;
    if (r0 >= n) return;
    int r1 = min(r0 + 1, n - 1);

    // ---------------- layer 1: [2 x P*32] @ [P*32 x 32] ----------------
    const ull* sb1u = (const ull*)sb1;
    ull a0[16], a1[16];
#pragma unroll
    for (int m = 0; m < 16; m++) { ull b = sb1u[m]; a0[m] = b; a1[m] = b; }

#pragma unroll
    for (int p = 0; p < P; p++) {
        const float4* x0;
        const float4* x1;
        if (p == 0) {
            x0 = (const float4*)(self + (size_t)r0 * 32);
            x1 = (const float4*)(self + (size_t)r1 * 32);
        } else if (GATHER) {
            const int* gi = (p == 1) ? gi0 : gi1;
            x0 = (const float4*)(other + (size_t)gi[r0] * 32);
            x1 = (const float4*)(other + (size_t)gi[r1] * 32);
        } else {
            x0 = (const float4*)(other + (size_t)r0 * 32);
            x1 = (const float4*)(other + (size_t)r1 * 32);
        }
#pragma unroll 2
        for (int k4 = 0; k4 < 8; k4++) {
            float4 v0 = x0[k4];
            float4 v1 = x1[k4];
            const float* e0 = (const float*)&v0;
            const float* e1 = (const float*)&v1;
#pragma unroll
            for (int kk = 0; kk < 4; kk++) {
                ull xp0 = pack2(e0[kk], e0[kk]);
                ull xp1 = pack2(e1[kk], e1[kk]);
                const ulonglong2* wr =
                    (const ulonglong2*)(sW1 + ((p * 8 + k4) * 4 + kk) * 32);
#pragma unroll
                for (int m2 = 0; m2 < 8; m2++) {
                    ulonglong2 w = wr[m2];
                    a0[2*m2]   = ffma2(xp0, w.x, a0[2*m2]);
                    a1[2*m2]   = ffma2(xp1, w.x, a1[2*m2]);
                    a0[2*m2+1] = ffma2(xp0, w.y, a0[2*m2+1]);
                    a1[2*m2+1] = ffma2(xp1, w.y, a1[2*m2+1]);
                }
            }
        }
    }

    // tanh on all pairs
#pragma unroll
    for (int m = 0; m < 16; m++) {
        float u, v;
        unpack2(a0[m], u, v); a0[m] = pack2(tanh_fast(u), tanh_fast(v));
        unpack2(a1[m], u, v); a1[m] = pack2(tanh_fast(u), tanh_fast(v));
    }

    // ---------------- layer 2: two 16-wide j-chunks ----------------
    const ull* sb2u = (const ull*)sb2;
    bool w1 = (r0 + 1 < n);
    float* O0 = out + (size_t)r0 * 32;
    float* O1 = out + (size_t)r1 * 32;

#pragma unroll
    for (int jc = 0; jc < 2; jc++) {
        ull o0[8], o1[8];
#pragma unroll
        for (int m = 0; m < 8; m++) {
            ull b = sb2u[jc * 8 + m];
            o0[m] = b; o1[m] = b;
        }
#pragma unroll 4
        for (int kp = 0; kp < 16; kp++) {   // k = 2*kp, 2*kp+1
            float ha0, hb0, ha1, hb1;
            unpack2(a0[kp], ha0, hb0);
            unpack2(a1[kp], ha1, hb1);
#pragma unroll
            for (int kh = 0; kh < 2; kh++) {
                ull xp0 = pack2(kh ? hb0 : ha0, kh ? hb0 : ha0);
                ull xp1 = pack2(kh ? hb1 : ha1, kh ? hb1 : ha1);
                const ulonglong2* wr =
                    (const ulonglong2*)(sW2 + (2 * kp + kh) * 32 + jc * 16);
#pragma unroll
                for (int m2 = 0; m2 < 4; m2++) {
                    ulonglong2 w = wr[m2];
                    o0[2*m2]   = ffma2(xp0, w.x, o0[2*m2]);
                    o1[2*m2]   = ffma2(xp1, w.x, o1[2*m2]);
                    o0[2*m2+1] = ffma2(xp0, w.y, o0[2*m2+1]);
                    o1[2*m2+1] = ffma2(xp1, w.y, o1[2*m2+1]);
                }
            }
        }

        float va[16], vb[16];
#pragma unroll
        for (int m = 0; m < 8; m++) {
            unpack2(o0[m], va[2*m], va[2*m+1]);
            unpack2(o1[m], vb[2*m], vb[2*m+1]);
        }
        float4* q0 = (float4*)(O0 + jc * 16);
        float4* q1 = (float4*)(O1 + jc * 16);
#pragma unroll
        for (int q = 0; q < 4; q++) {
            q0[q] = make_float4(va[4*q], va[4*q+1], va[4*q+2], va[4*q+3]);
            if (w1) q1[q] = make_float4(vb[4*q], vb[4*q+1], vb[4*q+2], vb[4*q+3]);
        }
    }
}

// ---------------------------------------------------------------------------
// acc[i0[r]] += src[r]; acc[i1[r]] += src[r]   (row-wise float4 atomics)
__global__ void __launch_bounds__(256) scatter2_kernel(
    const float* __restrict__ src,
    const int* __restrict__ i0, const int* __restrict__ i1,
    float* __restrict__ acc, int n)
{
    int r = blockIdx.x * 256 + threadIdx.x;
    if (r >= n) return;
    const float4* s = (const float4*)(src + (size_t)r * 32);
    float4* d0 = (float4*)(acc + (size_t)i0[r] * 32);
    float4* d1 = (float4*)(acc + (size_t)i1[r] * 32);
#pragma unroll
    for (int q = 0; q < 8; q++) {
        float4 v = s[q];
        atomicAdd(d0 + q, v);
        atomicAdd(d1 + q, v);
    }
}

// acc[dstidx[r]] += src[srcidx[r]]
__global__ void __launch_bounds__(256) scatter1_kernel(
    const float* __restrict__ src,
    const int* __restrict__ srcidx, const int* __restrict__ dstidx,
    float* __restrict__ acc, int n)
{
    int r = blockIdx.x * 256 + threadIdx.x;
    if (r >= n) return;
    const float4* s = (const float4*)(src + (size_t)srcidx[r] * 32);
    float4* d = (float4*)(acc + (size_t)dstidx[r] * 32);
#pragma unroll
    for (int q = 0; q < 8; q++) atomicAdd(d + q, s[q]);
}

// ---------------------------------------------------------------------------
static inline int nblk256(int n) { return (n + 255) / 256; }
static inline int nblk2(int n)   { return (n + 255) / 256; }  // 128 thr x 2 rows

extern "C" void kernel_launch(void* const* d_in, const int* in_sizes, int n_in,
                              void* d_out, int out_size)
{
    const float* h1     = (const float*)d_in[0];
    const float* h2     = (const float*)d_in[1];
    const float* h3     = (const float*)d_in[2];
    const float* h4     = (const float*)d_in[3];
    const float* upW1   = (const float*)d_in[4];
    const float* upb1   = (const float*)d_in[5];
    const float* upW2   = (const float*)d_in[6];
    const float* upb2   = (const float*)d_in[7];
    const float* dnW1   = (const float*)d_in[8];
    const float* dnb1   = (const float*)d_in[9];
    const float* dnW2   = (const float*)d_in[10];
    const float* dnb2   = (const float*)d_in[11];
    const float* rW1    = (const float*)d_in[12];
    const float* rb1    = (const float*)d_in[13];
    const float* rW2    = (const float*)d_in[14];
    const float* rb2    = (const float*)d_in[15];
    const int* idx2_0   = (const int*)d_in[16];
    const int* idx2_1   = (const int*)d_in[17];
    const int* idx3_0   = (const int*)d_in[18];
    const int* idx3_1   = (const int*)d_in[19];
    const int* idx4_0   = (const int*)d_in[20];
    const int* idx4_1   = (const int*)d_in[21];
    const int* ring_src = (const int*)d_in[22];
    const int* ring_dst = (const int*)d_in[23];

    const int N1 = in_sizes[0] / 32;
    const int N2 = in_sizes[1] / 32;
    const int N3 = in_sizes[2] / 32;
    const int N4 = in_sizes[3] / 32;
    const int ER = in_sizes[22];
    const int NR = out_size / 32 - (N1 + N2 + N3 + N4);

    float* out  = (float*)d_out;
    float* out1 = out;
    float* out2 = out1 + (size_t)N1 * 32;
    float* out3 = out2 + (size_t)N2 * 32;
    float* out4 = out3 + (size_t)N3 * 32;
    float* outR = out4 + (size_t)N4 * 32;

    float *h2buf, *h3buf, *acc3, *acc2, *acc1, *accr, *h1mid;
    cudaGetSymbolAddress((void**)&h2buf, g_h2);
    cudaGetSymbolAddress((void**)&h3buf, g_h3);
    cudaGetSymbolAddress((void**)&acc3,  g_acc3);
    cudaGetSymbolAddress((void**)&acc2,  g_acc2);
    cudaGetSymbolAddress((void**)&acc1,  g_acc1);
    cudaGetSymbolAddress((void**)&accr,  g_accr);
    cudaGetSymbolAddress((void**)&h1mid, g_h1mid);

    // ---- zero all accumulators once ----
    zero_multi_kernel<<<2048, 256>>>(
        (float4*)acc3, N3 * 8, (float4*)acc2, N2 * 8,
        (float4*)acc1, N1 * 8, (float4*)accr, N1 * 8,
        (float4*)outR, NR * 8);

    // ---- up pass ----
    mlp_jp2_kernel<3, true><<<nblk2(N2), 128>>>(h2, h1, idx2_0, idx2_1,
        upW1 + 0 * 96 * 32, upb1 + 0 * 32, upW2 + 0 * 1024, upb2 + 0 * 32,
        h2buf, N2);
    mlp_jp2_kernel<3, true><<<nblk2(N3), 128>>>(h3, h2buf, idx3_0, idx3_1,
        upW1 + 1 * 96 * 32, upb1 + 1 * 32, upW2 + 1 * 1024, upb2 + 1 * 32,
        h3buf, N3);
    mlp_jp2_kernel<3, true><<<nblk2(N4), 128>>>(h4, h3buf, idx4_0, idx4_1,
        upW1 + 2 * 96 * 32, upb1 + 2 * 32, upW2 + 2 * 1024, upb2 + 2 * 32,
        out4, N4);

    // ---- down pass ----
    scatter2_kernel<<<nblk256(N4), 256>>>(out4, idx4_0, idx4_1, acc3, N4);
    mlp_jp2_kernel<2, false><<<nblk2(N3), 128>>>(h3buf, acc3, 0, 0,
        dnW1 + 2 * 64 * 32, dnb1 + 2 * 32, dnW2 + 2 * 1024, dnb2 + 2 * 32,
        out3, N3);

    scatter2_kernel<<<nblk256(N3), 256>>>(out3, idx3_0, idx3_1, acc2, N3);
    mlp_jp2_kernel<2, false><<<nblk2(N2), 128>>>(h2buf, acc2, 0, 0,
        dnW1 + 1 * 64 * 32, dnb1 + 1 * 32, dnW2 + 1 * 1024, dnb2 + 1 * 32,
        out2, N2);

    scatter2_kernel<<<nblk256(N2), 256>>>(out2, idx2_0, idx2_1, acc1, N2);
    mlp_jp2_kernel<2, false><<<nblk2(N1), 128>>>(h1, acc1, 0, 0,
        dnW1 + 0 * 64 * 32, dnb1 + 0 * 32, dnW2 + 0 * 1024, dnb2 + 0 * 32,
        h1mid, N1);

    // ---- ring ----
    scatter1_kernel<<<nblk256(ER), 256>>>(h1mid, ring_src, ring_dst, outR, ER);
    scatter1_kernel<<<nblk256(ER), 256>>>(outR, ring_dst, ring_src, accr, ER);
    mlp_jp2_kernel<2, false><<<nblk2(N1), 128>>>(h1mid, accr, 0, 0,
        rW1, rb1, rW2, rb2, out1, N1);
}

// round 8
// speedup vs baseline: 1.6724x; 1.0267x over previous
#include <cuda_runtime.h>
#include <cstddef>

// ---------------------------------------------------------------------------
// HMP hierarchical message passing — R7 (resubmit after infra failure):
//  * 3 rows/thread j-pair f32x2 MLPs (weight-LDS amortized over 3 rows)
//  * layer 1 in two 16-j chunks (x re-streamed), layer 2 in four 8-j chunks
//    -> peak live regs ~150, __launch_bounds__(128,3) => 12 warps/SM, no spills
//  * separate scatter kernels, single upfront zero
// ---------------------------------------------------------------------------

typedef unsigned long long ull;

#define N1MAX 250000
#define N2MAX 500000
#define N3MAX 1000000

__device__ float g_h2   [(size_t)N2MAX * 32];
__device__ float g_h3   [(size_t)N3MAX * 32];
__device__ float g_acc3 [(size_t)N3MAX * 32];
__device__ float g_acc2 [(size_t)N2MAX * 32];
__device__ float g_acc1 [(size_t)N1MAX * 32];
__device__ float g_accr [(size_t)N1MAX * 32];
__device__ float g_h1mid[(size_t)N1MAX * 32];

// ---------------------------------------------------------------------------
__device__ __forceinline__ ull pack2(float lo, float hi)
{
    ull p;
    asm("mov.b64 %0, {%1, %2};" : "=l"(p) : "f"(lo), "f"(hi));
    return p;
}
__device__ __forceinline__ void unpack2(ull p, float& lo, float& hi)
{
    asm("mov.b64 {%0, %1}, %2;" : "=f"(lo), "=f"(hi) : "l"(p));
}
__device__ __forceinline__ ull ffma2(ull a, ull b, ull c)
{
    ull d;
    asm("fma.rn.f32x2 %0, %1, %2, %3;" : "=l"(d) : "l"(a), "l"(b), "l"(c));
    return d;
}

__device__ __forceinline__ float tanh_fast(float x)
{
    float cx = fminf(fmaxf(x, -15.f), 15.f);
    float e  = __expf(2.f * cx);
    return __fdividef(e - 1.f, e + 1.f);
}

// ---------------------------------------------------------------------------
__global__ void __launch_bounds__(256) zero_multi_kernel(
    float4* __restrict__ p0, int n0, float4* __restrict__ p1, int n1,
    float4* __restrict__ p2, int n2, float4* __restrict__ p3, int n3,
    float4* __restrict__ p4, int n4)
{
    const float4 z = make_float4(0.f, 0.f, 0.f, 0.f);
    int total = n0 + n1 + n2 + n3 + n4;
    for (int i = blockIdx.x * 256 + threadIdx.x; i < total; i += gridDim.x * 256) {
        int j = i;
        if (j < n0) { p0[j] = z; continue; } j -= n0;
        if (j < n1) { p1[j] = z; continue; } j -= n1;
        if (j < n2) { p2[j] = z; continue; } j -= n2;
        if (j < n3) { p3[j] = z; continue; } j -= n3;
        p4[j] = z;
    }
}

// ---------------------------------------------------------------------------
// 3 rows/thread MLP, j-pair layout, chunked layers.
// x = [ self[r] | blocks from 'other' ]; P = 2 or 3 input blocks of 32.
// GATHER: blocks 1,2 = other[gi0[r]], other[gi1[r]]; else block 1 = other[r].
// out[r] = tanh(x@W1+b1)@W2+b2
template<int P, bool GATHER>
__global__ void __launch_bounds__(128, 3) mlp_c_kernel(
    const float* __restrict__ self, const float* __restrict__ other,
    const int* __restrict__ gi0, const int* __restrict__ gi1,
    const float* __restrict__ W1, const float* __restrict__ b1,
    const float* __restrict__ W2, const float* __restrict__ b2,
    float* __restrict__ out, int n)
{
    __shared__ __align__(16) float sW1[P * 32 * 32];   // [K][32], native
    __shared__ __align__(16) float sW2[32 * 32];       // [k][j]
    __shared__ __align__(16) float sb1[32];
    __shared__ __align__(16) float sb2[32];
    for (int t = threadIdx.x; t < P * 32 * 32 / 4; t += 128)
        ((float4*)sW1)[t] = ((const float4*)W1)[t];
    for (int t = threadIdx.x; t < 32 * 32 / 4; t += 128)
        ((float4*)sW2)[t] = ((const float4*)W2)[t];
    if (threadIdx.x < 32) { sb1[threadIdx.x] = b1[threadIdx.x];
                            sb2[threadIdx.x] = b2[threadIdx.x]; }
    __syncthreads();

    int t  = blockIdx.x * 128 + threadIdx.x;
    int r0 = 3 * t;
    if (r0 >= n) return;
    int r1 = min(r0 + 1, n - 1);
    int r2 = min(r0 + 2, n - 1);

    // gathered indices (hoisted once)
    int g00 = 0, g01 = 0, g02 = 0, g10 = 0, g11 = 0, g12 = 0;
    if (GATHER) {
        g00 = gi0[r0]; g01 = gi0[r1]; g02 = gi0[r2];
        if (P == 3) { g10 = gi1[r0]; g11 = gi1[r1]; g12 = gi1[r2]; }
    }

    // h = tanh(x@W1+b1): 16 ull (j pairs) per row
    ull h0[16], h1[16], h2[16];

    const ull* sb1u = (const ull*)sb1;
    // ---------------- layer 1: two chunks of 16 output j ----------------
#pragma unroll
    for (int jc = 0; jc < 2; jc++) {
        ull c0[8], c1[8], c2[8];
#pragma unroll
        for (int m = 0; m < 8; m++) {
            ull b = sb1u[jc * 8 + m];
            c0[m] = b; c1[m] = b; c2[m] = b;
        }

#pragma unroll
        for (int p = 0; p < P; p++) {
            const float4* x0;
            const float4* x1;
            const float4* x2;
            if (p == 0) {
                x0 = (const float4*)(self + (size_t)r0 * 32);
                x1 = (const float4*)(self + (size_t)r1 * 32);
                x2 = (const float4*)(self + (size_t)r2 * 32);
            } else if (GATHER) {
                int a = (p == 1) ? g00 : g10;
                int b = (p == 1) ? g01 : g11;
                int c = (p == 1) ? g02 : g12;
                x0 = (const float4*)(other + (size_t)a * 32);
                x1 = (const float4*)(other + (size_t)b * 32);
                x2 = (const float4*)(other + (size_t)c * 32);
            } else {
                x0 = (const float4*)(other + (size_t)r0 * 32);
                x1 = (const float4*)(other + (size_t)r1 * 32);
                x2 = (const float4*)(other + (size_t)r2 * 32);
            }
#pragma unroll 2
            for (int k4 = 0; k4 < 8; k4++) {
                float4 v0 = x0[k4];
                float4 v1 = x1[k4];
                float4 v2 = x2[k4];
                const float* e0 = (const float*)&v0;
                const float* e1 = (const float*)&v1;
                const float* e2 = (const float*)&v2;
#pragma unroll
                for (int kk = 0; kk < 4; kk++) {
                    ull xp0 = pack2(e0[kk], e0[kk]);
                    ull xp1 = pack2(e1[kk], e1[kk]);
                    ull xp2 = pack2(e2[kk], e2[kk]);
                    const ulonglong2* wr = (const ulonglong2*)
                        (sW1 + ((p * 8 + k4) * 4 + kk) * 32 + jc * 16);
#pragma unroll
                    for (int m2 = 0; m2 < 4; m2++) {
                        ulonglong2 w = wr[m2];
                        c0[2*m2]   = ffma2(xp0, w.x, c0[2*m2]);
                        c1[2*m2]   = ffma2(xp1, w.x, c1[2*m2]);
                        c2[2*m2]   = ffma2(xp2, w.x, c2[2*m2]);
                        c0[2*m2+1] = ffma2(xp0, w.y, c0[2*m2+1]);
                        c1[2*m2+1] = ffma2(xp1, w.y, c1[2*m2+1]);
                        c2[2*m2+1] = ffma2(xp2, w.y, c2[2*m2+1]);
                    }
                }
            }
        }

        // tanh chunk -> h
#pragma unroll
        for (int m = 0; m < 8; m++) {
            float u, v;
            unpack2(c0[m], u, v); h0[jc*8+m] = pack2(tanh_fast(u), tanh_fast(v));
            unpack2(c1[m], u, v); h1[jc*8+m] = pack2(tanh_fast(u), tanh_fast(v));
            unpack2(c2[m], u, v); h2[jc*8+m] = pack2(tanh_fast(u), tanh_fast(v));
        }
    }

    // ---------------- layer 2: four chunks of 8 output j ----------------
    const ull* sb2u = (const ull*)sb2;
    bool w1e = (r0 + 1 < n), w2e = (r0 + 2 < n);
    float* O0 = out + (size_t)r0 * 32;
    float* O1 = out + (size_t)r1 * 32;
    float* O2 = out + (size_t)r2 * 32;

#pragma unroll
    for (int jc = 0; jc < 4; jc++) {
        ull o0[4], o1[4], o2[4];
#pragma unroll
        for (int m = 0; m < 4; m++) {
            ull b = sb2u[jc * 4 + m];
            o0[m] = b; o1[m] = b; o2[m] = b;
        }
#pragma unroll 4
        for (int kp = 0; kp < 16; kp++) {   // k = 2*kp, 2*kp+1
            float ha0, hb0, ha1, hb1, ha2, hb2;
            unpack2(h0[kp], ha0, hb0);
            unpack2(h1[kp], ha1, hb1);
            unpack2(h2[kp], ha2, hb2);
#pragma unroll
            for (int kh = 0; kh < 2; kh++) {
                ull xp0 = pack2(kh ? hb0 : ha0, kh ? hb0 : ha0);
                ull xp1 = pack2(kh ? hb1 : ha1, kh ? hb1 : ha1);
                ull xp2 = pack2(kh ? hb2 : ha2, kh ? hb2 : ha2);
                const ulonglong2* wr =
                    (const ulonglong2*)(sW2 + (2 * kp + kh) * 32 + jc * 8);
#pragma unroll
                for (int m2 = 0; m2 < 2; m2++) {
                    ulonglong2 w = wr[m2];
                    o0[2*m2]   = ffma2(xp0, w.x, o0[2*m2]);
                    o1[2*m2]   = ffma2(xp1, w.x, o1[2*m2]);
                    o2[2*m2]   = ffma2(xp2, w.x, o2[2*m2]);
                    o0[2*m2+1] = ffma2(xp0, w.y, o0[2*m2+1]);
                    o1[2*m2+1] = ffma2(xp1, w.y, o1[2*m2+1]);
                    o2[2*m2+1] = ffma2(xp2, w.y, o2[2*m2+1]);
                }
            }
        }

        float va[8], vb[8], vc[8];
#pragma unroll
        for (int m = 0; m < 4; m++) {
            unpack2(o0[m], va[2*m], va[2*m+1]);
            unpack2(o1[m], vb[2*m], vb[2*m+1]);
            unpack2(o2[m], vc[2*m], vc[2*m+1]);
        }
        float4* q0 = (float4*)(O0 + jc * 8);
        float4* q1 = (float4*)(O1 + jc * 8);
        float4* q2 = (float4*)(O2 + jc * 8);
#pragma unroll
        for (int q = 0; q < 2; q++) {
            q0[q] = make_float4(va[4*q], va[4*q+1], va[4*q+2], va[4*q+3]);
            if (w1e) q1[q] = make_float4(vb[4*q], vb[4*q+1], vb[4*q+2], vb[4*q+3]);
            if (w2e) q2[q] = make_float4(vc[4*q], vc[4*q+1], vc[4*q+2], vc[4*q+3]);
        }
    }
}

// ---------------------------------------------------------------------------
// acc[i0[r]] += src[r]; acc[i1[r]] += src[r]   (row-wise float4 atomics)
__global__ void __launch_bounds__(256) scatter2_kernel(
    const float* __restrict__ src,
    const int* __restrict__ i0, const int* __restrict__ i1,
    float* __restrict__ acc, int n)
{
    int r = blockIdx.x * 256 + threadIdx.x;
    if (r >= n) return;
    const float4* s = (const float4*)(src + (size_t)r * 32);
    float4* d0 = (float4*)(acc + (size_t)i0[r] * 32);
    float4* d1 = (float4*)(acc + (size_t)i1[r] * 32);
#pragma unroll
    for (int q = 0; q < 8; q++) {
        float4 v = s[q];
        atomicAdd(d0 + q, v);
        atomicAdd(d1 + q, v);
    }
}

// acc[dstidx[r]] += src[srcidx[r]]
__global__ void __launch_bounds__(256) scatter1_kernel(
    const float* __restrict__ src,
    const int* __restrict__ srcidx, const int* __restrict__ dstidx,
    float* __restrict__ acc, int n)
{
    int r = blockIdx.x * 256 + threadIdx.x;
    if (r >= n) return;
    const float4* s = (const float4*)(src + (size_t)srcidx[r] * 32);
    float4* d = (float4*)(acc + (size_t)dstidx[r] * 32);
#pragma unroll
    for (int q = 0; q < 8; q++) atomicAdd(d + q, s[q]);
}

// ---------------------------------------------------------------------------
static inline int nblk256(int n) { return (n + 255) / 256; }
static inline int nblk3(int n)   { return (n + 383) / 384; }  // 128 thr x 3 rows

extern "C" void kernel_launch(void* const* d_in, const int* in_sizes, int n_in,
                              void* d_out, int out_size)
{
    const float* h1     = (const float*)d_in[0];
    const float* h2     = (const float*)d_in[1];
    const float* h3     = (const float*)d_in[2];
    const float* h4     = (const float*)d_in[3];
    const float* upW1   = (const float*)d_in[4];
    const float* upb1   = (const float*)d_in[5];
    const float* upW2   = (const float*)d_in[6];
    const float* upb2   = (const float*)d_in[7];
    const float* dnW1   = (const float*)d_in[8];
    const float* dnb1   = (const float*)d_in[9];
    const float* dnW2   = (const float*)d_in[10];
    const float* dnb2   = (const float*)d_in[11];
    const float* rW1    = (const float*)d_in[12];
    const float* rb1    = (const float*)d_in[13];
    const float* rW2    = (const float*)d_in[14];
    const float* rb2    = (const float*)d_in[15];
    const int* idx2_0   = (const int*)d_in[16];
    const int* idx2_1   = (const int*)d_in[17];
    const int* idx3_0   = (const int*)d_in[18];
    const int* idx3_1   = (const int*)d_in[19];
    const int* idx4_0   = (const int*)d_in[20];
    const int* idx4_1   = (const int*)d_in[21];
    const int* ring_src = (const int*)d_in[22];
    const int* ring_dst = (const int*)d_in[23];

    const int N1 = in_sizes[0] / 32;
    const int N2 = in_sizes[1] / 32;
    const int N3 = in_sizes[2] / 32;
    const int N4 = in_sizes[3] / 32;
    const int ER = in_sizes[22];
    const int NR = out_size / 32 - (N1 + N2 + N3 + N4);

    float* out  = (float*)d_out;
    float* out1 = out;
    float* out2 = out1 + (size_t)N1 * 32;
    float* out3 = out2 + (size_t)N2 * 32;
    float* out4 = out3 + (size_t)N3 * 32;
    float* outR = out4 + (size_t)N4 * 32;

    float *h2buf, *h3buf, *acc3, *acc2, *acc1, *accr, *h1mid;
    cudaGetSymbolAddress((void**)&h2buf, g_h2);
    cudaGetSymbolAddress((void**)&h3buf, g_h3);
    cudaGetSymbolAddress((void**)&acc3,  g_acc3);
    cudaGetSymbolAddress((void**)&acc2,  g_acc2);
    cudaGetSymbolAddress((void**)&acc1,  g_acc1);
    cudaGetSymbolAddress((void**)&accr,  g_accr);
    cudaGetSymbolAddress((void**)&h1mid, g_h1mid);

    // ---- zero all accumulators once ----
    zero_multi_kernel<<<2048, 256>>>(
        (float4*)acc3, N3 * 8, (float4*)acc2, N2 * 8,
        (float4*)acc1, N1 * 8, (float4*)accr, N1 * 8,
        (float4*)outR, NR * 8);

    // ---- up pass ----
    mlp_c_kernel<3, true><<<nblk3(N2), 128>>>(h2, h1, idx2_0, idx2_1,
        upW1 + 0 * 96 * 32, upb1 + 0 * 32, upW2 + 0 * 1024, upb2 + 0 * 32,
        h2buf, N2);
    mlp_c_kernel<3, true><<<nblk3(N3), 128>>>(h3, h2buf, idx3_0, idx3_1,
        upW1 + 1 * 96 * 32, upb1 + 1 * 32, upW2 + 1 * 1024, upb2 + 1 * 32,
        h3buf, N3);
    mlp_c_kernel<3, true><<<nblk3(N4), 128>>>(h4, h3buf, idx4_0, idx4_1,
        upW1 + 2 * 96 * 32, upb1 + 2 * 32, upW2 + 2 * 1024, upb2 + 2 * 32,
        out4, N4);

    // ---- down pass ----
    scatter2_kernel<<<nblk256(N4), 256>>>(out4, idx4_0, idx4_1, acc3, N4);
    mlp_c_kernel<2, false><<<nblk3(N3), 128>>>(h3buf, acc3, 0, 0,
        dnW1 + 2 * 64 * 32, dnb1 + 2 * 32, dnW2 + 2 * 1024, dnb2 + 2 * 32,
        out3, N3);

    scatter2_kernel<<<nblk256(N3), 256>>>(out3, idx3_0, idx3_1, acc2, N3);
    mlp_c_kernel<2, false><<<nblk3(N2), 128>>>(h2buf, acc2, 0, 0,
        dnW1 + 1 * 64 * 32, dnb1 + 1 * 32, dnW2 + 1 * 1024, dnb2 + 1 * 32,
        out2, N2);

    scatter2_kernel<<<nblk256(N2), 256>>>(out2, idx2_0, idx2_1, acc1, N2);
    mlp_c_kernel<2, false><<<nblk3(N1), 128>>>(h1, acc1, 0, 0,
        dnW1 + 0 * 64 * 32, dnb1 + 0 * 32, dnW2 + 0 * 1024, dnb2 + 0 * 32,
        h1mid, N1);

    // ---- ring ----
    scatter1_kernel<<<nblk256(ER), 256>>>(h1mid, ring_src, ring_dst, outR, ER);
    scatter1_kernel<<<nblk256(ER), 256>>>(outR, ring_dst, ring_src, accr, ER);
    mlp_c_kernel<2, false><<<nblk3(N1), 128>>>(h1mid, accr, 0, 0,
        rW1, rb1, rW2, rb2, out1, N1);
}